// round 1
// baseline (speedup 1.0000x reference)
#include <cuda_runtime.h>
#include <math.h>

// Problem constants
#define BB 2
#define SS 4096
#define DD 2048
#define MM (BB * SS)          // 8192 rows for the GEMMs
#define MN ((size_t)MM * DD)  // 16777216 elements per tensor
#define CH 64                 // scan chunks
#define CL (SS / CH)          // 64 steps per chunk

// ---------------- scratch (static device memory; no runtime allocs) -------
__device__ float g_gate[MN];   // gate_input
__device__ float g_alpha[MN];  // sigmoid(G@Wa + ba)
__device__ float g_x[MN];      // first silu(G@Wb + bb), then x = v*beta*ws
__device__ float g_Ac[BB * CH * DD];
__device__ float g_Xc[BB * CH * DD];
__device__ float g_Hin[BB * CH * DD];

// ---------------- K0: gate_input = rms_norm(c) + rms_norm(prev) -----------
__global__ __launch_bounds__(256) void k_rmsnorm_add(
    const float* __restrict__ c, const float* __restrict__ p) {
  const int row = blockIdx.x;        // 0..8191
  const int tid = threadIdx.x;       // 256 threads
  const float4* c4 = (const float4*)(c + (size_t)row * DD);
  const float4* p4 = (const float4*)(p + (size_t)row * DD);
  float4* g4 = (float4*)(g_gate + (size_t)row * DD);

  // 512 float4 per row, 2 per thread
  float4 cv0 = c4[tid], cv1 = c4[tid + 256];
  float4 pv0 = p4[tid], pv1 = p4[tid + 256];

  float sc = cv0.x * cv0.x + cv0.y * cv0.y + cv0.z * cv0.z + cv0.w * cv0.w +
             cv1.x * cv1.x + cv1.y * cv1.y + cv1.z * cv1.z + cv1.w * cv1.w;
  float sp = pv0.x * pv0.x + pv0.y * pv0.y + pv0.z * pv0.z + pv0.w * pv0.w +
             pv1.x * pv1.x + pv1.y * pv1.y + pv1.z * pv1.z + pv1.w * pv1.w;

#pragma unroll
  for (int off = 16; off > 0; off >>= 1) {
    sc += __shfl_xor_sync(0xffffffffu, sc, off);
    sp += __shfl_xor_sync(0xffffffffu, sp, off);
  }
  __shared__ float ssc[8], ssp[8];
  if ((tid & 31) == 0) { ssc[tid >> 5] = sc; ssp[tid >> 5] = sp; }
  __syncthreads();
  float tc = 0.f, tp = 0.f;
#pragma unroll
  for (int i = 0; i < 8; i++) { tc += ssc[i]; tp += ssp[i]; }

  const float rc = rsqrtf(tc * (1.0f / DD) + 1e-6f);
  const float rp = rsqrtf(tp * (1.0f / DD) + 1e-6f);

  float4 o0, o1;
  o0.x = cv0.x * rc + pv0.x * rp; o0.y = cv0.y * rc + pv0.y * rp;
  o0.z = cv0.z * rc + pv0.z * rp; o0.w = cv0.w * rc + pv0.w * rp;
  o1.x = cv1.x * rc + pv1.x * rp; o1.y = cv1.y * rc + pv1.y * rp;
  o1.z = cv1.z * rc + pv1.z * rp; o1.w = cv1.w * rc + pv1.w * rp;
  g4[tid] = o0; g4[tid + 256] = o1;
}

// ---------------- K1: dual GEMM (alpha & beta), fused activations ---------
// grid.x = 32 virtual N-tiles (0..15 -> W_alpha/sigmoid, 16..31 -> W_beta/silu)
// grid.y = 64 M-tiles. 128x128x16 tile, 256 threads, 8x8 per thread.
__global__ __launch_bounds__(256) void k_gemm_gates(
    const float* __restrict__ Wa, const float* __restrict__ ba,
    const float* __restrict__ Wb, const float* __restrict__ bb) {
  const int K = DD, N = DD;
  const int bnv = blockIdx.x;
  const int bm = blockIdx.y;
  const bool isBeta = (bnv >= 16);
  const float* __restrict__ W = isBeta ? Wb : Wa;
  const float* __restrict__ bias = isBeta ? bb : ba;
  const int ncol0 = (isBeta ? bnv - 16 : bnv) * 128;

  __shared__ float As[16][128];
  __shared__ float Bs[16][128];

  const int tid = threadIdx.x;
  const int wm = tid >> 4;   // 0..15 (row group)
  const int wn = tid & 15;   // 0..15 (col group)

  float acc[8][8];
#pragma unroll
  for (int i = 0; i < 8; i++)
#pragma unroll
    for (int j = 0; j < 8; j++) acc[i][j] = 0.f;

  const float* Gp = g_gate;

  for (int kt = 0; kt < K; kt += 16) {
    // load A tile (128x16) transposed into As[k][m]
#pragma unroll
    for (int i = 0; i < 2; i++) {
      int id = tid * 2 + i;         // 0..511
      int m = id >> 2;              // 0..127
      int k4 = (id & 3) * 4;        // 0,4,8,12
      float4 v = *(const float4*)(Gp + ((size_t)(bm * 128 + m)) * K + kt + k4);
      As[k4 + 0][m] = v.x; As[k4 + 1][m] = v.y;
      As[k4 + 2][m] = v.z; As[k4 + 3][m] = v.w;
    }
    // load B tile (16x128)
#pragma unroll
    for (int i = 0; i < 2; i++) {
      int id = tid * 2 + i;         // 0..511
      int r = id >> 5;              // 0..15
      int c4 = (id & 31) * 4;       // 0..124
      *(float4*)(&Bs[r][c4]) =
          *(const float4*)(W + ((size_t)(kt + r)) * N + ncol0 + c4);
    }
    __syncthreads();

#pragma unroll
    for (int k = 0; k < 16; k++) {
      float a[8], b[8];
#pragma unroll
      for (int i = 0; i < 8; i++) a[i] = As[k][wm * 8 + i];
#pragma unroll
      for (int j = 0; j < 8; j++) b[j] = Bs[k][wn * 8 + j];
#pragma unroll
      for (int i = 0; i < 8; i++)
#pragma unroll
        for (int j = 0; j < 8; j++) acc[i][j] = fmaf(a[i], b[j], acc[i][j]);
    }
    __syncthreads();
  }

  float* __restrict__ dst = isBeta ? g_x : g_alpha;
#pragma unroll
  for (int i = 0; i < 8; i++) {
    const size_t m = (size_t)(bm * 128 + wm * 8 + i);
#pragma unroll
    for (int j = 0; j < 8; j++) {
      const int n = ncol0 + wn * 8 + j;
      float pre = acc[i][j] + __ldg(&bias[n]);
      float sg = 1.0f / (1.0f + __expf(-pre));
      float r = isBeta ? (pre * sg) : sg;   // silu vs sigmoid
      dst[m * N + n] = r;
    }
  }
}

// ---------------- K2: x = v * beta * sqrt(max(1 - a*a, 1e-6)) -------------
__global__ __launch_bounds__(256) void k_compute_x(const float* __restrict__ v) {
  size_t i = ((size_t)blockIdx.x * blockDim.x + threadIdx.x);
  size_t n4 = MN / 4;
  if (i >= n4) return;
  float4 bv = ((const float4*)g_x)[i];
  float4 av = ((const float4*)g_alpha)[i];
  float4 vv = ((const float4*)v)[i];
  float4 o;
  o.x = vv.x * bv.x * sqrtf(fmaxf(1.0f - av.x * av.x, 1e-6f));
  o.y = vv.y * bv.y * sqrtf(fmaxf(1.0f - av.y * av.y, 1e-6f));
  o.z = vv.z * bv.z * sqrtf(fmaxf(1.0f - av.z * av.z, 1e-6f));
  o.w = vv.w * bv.w * sqrtf(fmaxf(1.0f - av.w * av.w, 1e-6f));
  ((float4*)g_x)[i] = o;
}

// ---------------- K3a: per-chunk (A_prod, X_scan) --------------------------
__global__ __launch_bounds__(256) void k_scan_chunks() {
  const int d = blockIdx.x * 256 + threadIdx.x;
  const int ch = blockIdx.y;
  const int b = blockIdx.z;
  size_t base = ((size_t)(b * SS + ch * CL)) * DD + d;
  float A = 1.f, X = 0.f;
#pragma unroll 4
  for (int t = 0; t < CL; t++) {
    size_t idx = base + (size_t)t * DD;
    float a = g_alpha[idx];
    float x = g_x[idx];
    X = fmaf(a, X, x);
    A *= a;
  }
  const int o = (b * CH + ch) * DD + d;
  g_Ac[o] = A;
  g_Xc[o] = X;
}

// ---------------- K3b: carry scan across chunks ----------------------------
__global__ __launch_bounds__(256) void k_scan_carry() {
  const int g = blockIdx.x * 256 + threadIdx.x;  // 0..4095
  const int b = g / DD;
  const int d = g % DD;
  float H = 0.f;
#pragma unroll 4
  for (int c = 0; c < CH; c++) {
    const int idx = (b * CH + c) * DD + d;
    g_Hin[idx] = H;
    H = fmaf(g_Ac[idx], H, g_Xc[idx]);
  }
}

// ---------------- K3c: final rescan + outputs ------------------------------
__global__ __launch_bounds__(256) void k_scan_final(
    const float* __restrict__ v, const float* __restrict__ outp,
    const float* __restrict__ cin, const float* __restrict__ gout,
    const float* __restrict__ gv, float* __restrict__ o_v,
    float* __restrict__ o_out, float* __restrict__ o_c,
    float* __restrict__ o_f) {
  const int d = blockIdx.x * 256 + threadIdx.x;
  const int ch = blockIdx.y;
  const int b = blockIdx.z;
  size_t base = ((size_t)(b * SS + ch * CL)) * DD + d;
  float h = g_Hin[(b * CH + ch) * DD + d];
  const float go = __ldg(&gout[d]);
  const float gvv = __ldg(&gv[d]);
#pragma unroll 4
  for (int t = 0; t < CL; t++) {
    size_t idx = base + (size_t)t * DD;
    float a = g_alpha[idx];
    float x = g_x[idx];
    h = fmaf(a, h, x);
    o_f[idx] = h;
    o_v[idx] = fmaf(h, gvv, v[idx]);
    o_out[idx] = fmaf(h, go, outp[idx]);
    o_c[idx] = cin[idx];
  }
}

// ---------------- launch ----------------------------------------------------
extern "C" void kernel_launch(void* const* d_in, const int* in_sizes, int n_in,
                              void* d_out, int out_size) {
  const float* v = (const float*)d_in[0];
  const float* out = (const float*)d_in[1];
  const float* c = (const float*)d_in[2];
  const float* prev = (const float*)d_in[3];
  const float* Wa = (const float*)d_in[4];
  const float* ba = (const float*)d_in[5];
  const float* Wb = (const float*)d_in[6];
  const float* bb = (const float*)d_in[7];
  const float* gout = (const float*)d_in[8];
  const float* gv = (const float*)d_in[9];

  float* o_v = (float*)d_out;
  float* o_out = o_v + MN;
  float* o_c = o_out + MN;
  float* o_f = o_c + MN;

  // K0: gate_input
  k_rmsnorm_add<<<MM, 256>>>(c, prev);

  // K1: dual fused GEMM
  dim3 ggrid(32, 64);
  k_gemm_gates<<<ggrid, 256>>>(Wa, ba, Wb, bb);

  // K2: x
  {
    size_t n4 = MN / 4;
    int blocks = (int)((n4 + 255) / 256);
    k_compute_x<<<blocks, 256>>>(v);
  }

  // K3: chunked scan
  dim3 agrid(DD / 256, CH, BB);
  k_scan_chunks<<<agrid, 256>>>();
  k_scan_carry<<<(BB * DD) / 256, 256>>>();
  k_scan_final<<<agrid, 256>>>(v, out, c, gout, gv, o_v, o_out, o_c, o_f);
}

// round 3
// speedup vs baseline: 2.2074x; 2.2074x over previous
#include <cuda_runtime.h>
#include <cuda_bf16.h>
#include <math.h>
#include <stdint.h>

// Problem constants
#define BB 2
#define SS 4096
#define DD 2048
#define MM (BB * SS)          // 8192 GEMM rows
#define MN ((size_t)MM * DD)  // elements per tensor
#define CH 64                 // scan chunks
#define CL (SS / CH)          // steps per chunk

#define Bb_M 128
#define Bb_N 128
#define Bb_K 32
#define KITERS 192            // 3 * 2048 / 32  (bf16x3 split folded into K)

// ---------------- scratch (static device memory) ---------------------------
__device__ __align__(256) __nv_bfloat16 g_gA_hi[MN];
__device__ __align__(256) __nv_bfloat16 g_gA_lo[MN];
__device__ __align__(256) __nv_bfloat16 g_WaT_hi[(size_t)DD * DD];
__device__ __align__(256) __nv_bfloat16 g_WaT_lo[(size_t)DD * DD];
__device__ __align__(256) __nv_bfloat16 g_WbT_hi[(size_t)DD * DD];
__device__ __align__(256) __nv_bfloat16 g_WbT_lo[(size_t)DD * DD];
__device__ __align__(256) float g_alpha[MN];  // sigmoid gate
__device__ __align__(256) float g_beta[MN];   // silu gate
__device__ __align__(256) float g_Ac[BB * CH * DD];
__device__ __align__(256) float g_Xc[BB * CH * DD];
__device__ __align__(256) float g_Hin[BB * CH * DD];

// ---------------- PTX helpers ----------------------------------------------
static __device__ __forceinline__ uint32_t smem_u32(const void* p) {
  uint32_t a;
  asm("{ .reg .u64 t; cvta.to.shared.u64 t, %1; cvt.u32.u64 %0, t; }"
      : "=r"(a) : "l"(p));
  return a;
}

static __device__ __forceinline__ void cpa16(uint32_t dst, const void* src) {
  asm volatile("cp.async.cg.shared.global [%0], [%1], 16;" :: "r"(dst), "l"(src));
}
#define CPA_COMMIT() asm volatile("cp.async.commit_group;" ::: "memory")
#define CPA_WAIT1() asm volatile("cp.async.wait_group 1;" ::: "memory")

static __device__ __forceinline__ void ldmx4(uint32_t* r, uint32_t addr) {
  asm volatile(
      "ldmatrix.sync.aligned.m8n8.x4.shared.b16 {%0, %1, %2, %3}, [%4];"
      : "=r"(r[0]), "=r"(r[1]), "=r"(r[2]), "=r"(r[3]) : "r"(addr));
}

static __device__ __forceinline__ void mma16816(
    float* d, const uint32_t* a, uint32_t b0, uint32_t b1) {
  asm volatile(
      "mma.sync.aligned.m16n8k16.row.col.f32.bf16.bf16.f32 "
      "{%0, %1, %2, %3}, {%4, %5, %6, %7}, {%8, %9}, {%0, %1, %2, %3};"
      : "+f"(d[0]), "+f"(d[1]), "+f"(d[2]), "+f"(d[3])
      : "r"(a[0]), "r"(a[1]), "r"(a[2]), "r"(a[3]), "r"(b0), "r"(b1));
}

// ---------------- K0: gate = rms(c)+rms(prev), split to bf16 hi/lo ----------
static __device__ __forceinline__ void split2(float a, float b,
                                              __nv_bfloat162& h, __nv_bfloat162& l) {
  __nv_bfloat16 ha = __float2bfloat16(a), hb = __float2bfloat16(b);
  h = __halves2bfloat162(ha, hb);
  l = __halves2bfloat162(__float2bfloat16(a - __bfloat162float(ha)),
                         __float2bfloat16(b - __bfloat162float(hb)));
}

__global__ __launch_bounds__(256) void k_rmsnorm_split(
    const float* __restrict__ c, const float* __restrict__ p) {
  const int row = blockIdx.x;
  const int tid = threadIdx.x;
  const float4* c4 = (const float4*)(c + (size_t)row * DD);
  const float4* p4 = (const float4*)(p + (size_t)row * DD);

  float4 cv0 = c4[tid], cv1 = c4[tid + 256];
  float4 pv0 = p4[tid], pv1 = p4[tid + 256];

  float sc = cv0.x * cv0.x + cv0.y * cv0.y + cv0.z * cv0.z + cv0.w * cv0.w +
             cv1.x * cv1.x + cv1.y * cv1.y + cv1.z * cv1.z + cv1.w * cv1.w;
  float sp = pv0.x * pv0.x + pv0.y * pv0.y + pv0.z * pv0.z + pv0.w * pv0.w +
             pv1.x * pv1.x + pv1.y * pv1.y + pv1.z * pv1.z + pv1.w * pv1.w;
#pragma unroll
  for (int off = 16; off > 0; off >>= 1) {
    sc += __shfl_xor_sync(0xffffffffu, sc, off);
    sp += __shfl_xor_sync(0xffffffffu, sp, off);
  }
  __shared__ float ssc[8], ssp[8];
  if ((tid & 31) == 0) { ssc[tid >> 5] = sc; ssp[tid >> 5] = sp; }
  __syncthreads();
  float tc = 0.f, tp = 0.f;
#pragma unroll
  for (int i = 0; i < 8; i++) { tc += ssc[i]; tp += ssp[i]; }
  const float rc = rsqrtf(tc * (1.0f / DD) + 1e-6f);
  const float rp = rsqrtf(tp * (1.0f / DD) + 1e-6f);

  float o[8];
  o[0] = cv0.x * rc + pv0.x * rp; o[1] = cv0.y * rc + pv0.y * rp;
  o[2] = cv0.z * rc + pv0.z * rp; o[3] = cv0.w * rc + pv0.w * rp;
  o[4] = cv1.x * rc + pv1.x * rp; o[5] = cv1.y * rc + pv1.y * rp;
  o[6] = cv1.z * rc + pv1.z * rp; o[7] = cv1.w * rc + pv1.w * rp;

  __nv_bfloat162* h2 = (__nv_bfloat162*)(g_gA_hi + (size_t)row * DD);
  __nv_bfloat162* l2 = (__nv_bfloat162*)(g_gA_lo + (size_t)row * DD);
  __nv_bfloat162 h, l;
  split2(o[0], o[1], h, l); h2[2 * tid + 0] = h; l2[2 * tid + 0] = l;
  split2(o[2], o[3], h, l); h2[2 * tid + 1] = h; l2[2 * tid + 1] = l;
  split2(o[4], o[5], h, l); h2[2 * (tid + 256) + 0] = h; l2[2 * (tid + 256) + 0] = l;
  split2(o[6], o[7], h, l); h2[2 * (tid + 256) + 1] = h; l2[2 * (tid + 256) + 1] = l;
}

// ---------------- K_w: transpose + bf16 split of W --------------------------
__global__ __launch_bounds__(256) void k_cvt_w(
    const float* __restrict__ Wa, const float* __restrict__ Wb) {
  __shared__ float t[32][33];
  const int mat = blockIdx.z;
  const float* __restrict__ W = mat ? Wb : Wa;
  __nv_bfloat16* __restrict__ Th = mat ? g_WbT_hi : g_WaT_hi;
  __nv_bfloat16* __restrict__ Tl = mat ? g_WbT_lo : g_WaT_lo;
  const int bx = blockIdx.x * 32;  // n base
  const int by = blockIdx.y * 32;  // k base
  const int x = threadIdx.x & 31, y0 = threadIdx.x >> 5;
#pragma unroll
  for (int i = 0; i < 4; i++) {
    int y = y0 + i * 8;
    t[y][x] = W[(size_t)(by + y) * DD + bx + x];  // W[k][n]
  }
  __syncthreads();
#pragma unroll
  for (int i = 0; i < 4; i++) {
    int y = y0 + i * 8;
    float v = t[x][y];  // WT[n=bx+y][k=by+x]
    __nv_bfloat16 h = __float2bfloat16(v);
    size_t idx = (size_t)(bx + y) * DD + by + x;
    Th[idx] = h;
    Tl[idx] = __float2bfloat16(v - __bfloat162float(h));
  }
}

// ---------------- K1: mma.sync dual GEMM, bf16x3, fused activations ---------
// grid.x: 0..15 -> W_alpha/sigmoid N-tiles, 16..31 -> W_beta/silu N-tiles
// grid.y: 64 M-tiles. 128x128x32 CTA tile, 8 warps each 64x32.
__global__ __launch_bounds__(256, 2) void k_gemm_mma(
    const float* __restrict__ ba, const float* __restrict__ bb) {
  __shared__ __align__(1024) char sm[3 * 16384];  // 3 stages x (8KB A + 8KB B)
  const uint32_t smb = smem_u32(sm);

  const int tid = threadIdx.x;
  const int wid = tid >> 5, lid = tid & 31;
  const int bxv = blockIdx.x;
  const bool isBeta = (bxv >= 16);
  const int n0 = (isBeta ? bxv - 16 : bxv) * Bb_N;
  const int m0 = blockIdx.y * Bb_M;
  const __nv_bfloat16* __restrict__ Bhi = isBeta ? g_WbT_hi : g_WaT_hi;
  const __nv_bfloat16* __restrict__ Blo = isBeta ? g_WbT_lo : g_WaT_lo;
  const float* __restrict__ bias = isBeta ? bb : ba;

  // cp.async slots: 2 A chunks + 2 B chunks of 16B per thread per stage
  uint32_t a_sm[2], b_sm[2];
  size_t a_gl[2], b_gl[2];
#pragma unroll
  for (int i = 0; i < 2; i++) {
    int id = tid + i * 256;      // 0..511
    int row = id >> 2, cc = id & 3;
    uint32_t sw = (uint32_t)((cc ^ ((row >> 1) & 3)) << 4);
    a_sm[i] = row * 64 + sw;
    b_sm[i] = row * 64 + sw;
    a_gl[i] = (size_t)(m0 + row) * DD + cc * 8;
    b_gl[i] = (size_t)(n0 + row) * DD + cc * 8;
  }

  auto load_stage = [&](int kc, int buf) {
    const int seg = kc >> 6;            // 64 k-chunks per segment
    const int kk = (kc & 63) * Bb_K;
    const __nv_bfloat16* __restrict__ As = (seg == 1) ? g_gA_lo : g_gA_hi;
    const __nv_bfloat16* __restrict__ Bs = (seg == 2) ? Blo : Bhi;
    const uint32_t ab = smb + buf * 16384;
    const uint32_t bbuf = ab + 8192;
#pragma unroll
    for (int i = 0; i < 2; i++) cpa16(ab + a_sm[i], As + a_gl[i] + kk);
#pragma unroll
    for (int i = 0; i < 2; i++) cpa16(bbuf + b_sm[i], Bs + b_gl[i] + kk);
  };

  // warp tiling: wm in {0,1} (64 rows), wn in {0..3} (32 cols)
  const int wm = wid & 1, wn = wid >> 1;
  const int lr = lid & 15, c8 = lid >> 4;

  uint32_t a_off[4], a_swz[4];
#pragma unroll
  for (int mt = 0; mt < 4; mt++) {
    int row = wm * 64 + mt * 16 + lr;
    a_off[mt] = row * 64;
    a_swz[mt] = (row >> 1) & 3;
  }
  uint32_t b_off[2], b_swz[2];
#pragma unroll
  for (int bt = 0; bt < 2; bt++) {
    int row = wn * 32 + bt * 16 + lr;
    b_off[bt] = row * 64;
    b_swz[bt] = (row >> 1) & 3;
  }

  float ac[4][4][4];
#pragma unroll
  for (int i = 0; i < 4; i++)
#pragma unroll
    for (int j = 0; j < 4; j++)
#pragma unroll
      for (int q = 0; q < 4; q++) ac[i][j][q] = 0.f;

  load_stage(0, 0); CPA_COMMIT();
  load_stage(1, 1); CPA_COMMIT();

#pragma unroll 1
  for (int kc = 0; kc < KITERS; kc++) {
    CPA_WAIT1();
    __syncthreads();

    if (kc + 2 < KITERS) load_stage(kc + 2, (kc + 2) % 3);
    CPA_COMMIT();

    const uint32_t abase = smb + (kc % 3) * 16384;
    const uint32_t bbase = abase + 8192;

#pragma unroll
    for (int ks = 0; ks < 2; ks++) {
      uint32_t af[4][4], bfr[2][4];
#pragma unroll
      for (int mt = 0; mt < 4; mt++) {
        uint32_t chunk = (uint32_t)(ks * 2 + c8);
        ldmx4(af[mt], abase + a_off[mt] + (((chunk ^ a_swz[mt])) << 4));
      }
#pragma unroll
      for (int bt = 0; bt < 2; bt++) {
        uint32_t chunk = (uint32_t)(ks * 2 + c8);
        ldmx4(bfr[bt], bbase + b_off[bt] + (((chunk ^ b_swz[bt])) << 4));
      }
#pragma unroll
      for (int mt = 0; mt < 4; mt++) {
#pragma unroll
        for (int nt = 0; nt < 4; nt++) {
          const int bt = nt >> 1, sel = nt & 1;
          mma16816(ac[mt][nt], af[mt], bfr[bt][sel], bfr[bt][2 + sel]);
        }
      }
    }
  }

  // epilogue: bias + sigmoid/silu, direct global store
  float* __restrict__ dst = isBeta ? g_beta : g_alpha;
  const int g = lid >> 2, tig = lid & 3;
  float bi0[4], bi1[4];
#pragma unroll
  for (int nt = 0; nt < 4; nt++) {
    int col = n0 + wn * 32 + nt * 8 + tig * 2;
    bi0[nt] = __ldg(bias + col);
    bi1[nt] = __ldg(bias + col + 1);
  }
#pragma unroll
  for (int mt = 0; mt < 4; mt++) {
    const int row = m0 + wm * 64 + mt * 16 + g;
#pragma unroll
    for (int nt = 0; nt < 4; nt++) {
      const int col = n0 + wn * 32 + nt * 8 + tig * 2;
      float pr, sg;
      float2 v0, v1;
      pr = ac[mt][nt][0] + bi0[nt];
      sg = 1.0f / (1.0f + __expf(-pr)); v0.x = isBeta ? pr * sg : sg;
      pr = ac[mt][nt][1] + bi1[nt];
      sg = 1.0f / (1.0f + __expf(-pr)); v0.y = isBeta ? pr * sg : sg;
      pr = ac[mt][nt][2] + bi0[nt];
      sg = 1.0f / (1.0f + __expf(-pr)); v1.x = isBeta ? pr * sg : sg;
      pr = ac[mt][nt][3] + bi1[nt];
      sg = 1.0f / (1.0f + __expf(-pr)); v1.y = isBeta ? pr * sg : sg;
      *(float2*)(dst + (size_t)row * DD + col) = v0;
      *(float2*)(dst + (size_t)(row + 8) * DD + col) = v1;
    }
  }
}

// ---------------- x helper ---------------------------------------------------
static __device__ __forceinline__ float x_of(float a, float be, float vv) {
  return vv * be * sqrtf(fmaxf(1.0f - a * a, 1e-6f));
}

// ---------------- K3a: per-chunk (A_prod, X_scan), x fused -------------------
__global__ __launch_bounds__(256) void k_scan_chunks(const float* __restrict__ v) {
  const int d = blockIdx.x * 256 + threadIdx.x;
  const int ch = blockIdx.y;
  const int b = blockIdx.z;
  size_t base = ((size_t)(b * SS + ch * CL)) * DD + d;
  float A = 1.f, X = 0.f;
#pragma unroll 4
  for (int t = 0; t < CL; t++) {
    size_t idx = base + (size_t)t * DD;
    float a = g_alpha[idx];
    float x = x_of(a, g_beta[idx], v[idx]);
    X = fmaf(a, X, x);
    A *= a;
  }
  const int o = (b * CH + ch) * DD + d;
  g_Ac[o] = A;
  g_Xc[o] = X;
}

// ---------------- K3b: carry scan across chunks ------------------------------
__global__ __launch_bounds__(256) void k_scan_carry() {
  const int g = blockIdx.x * 256 + threadIdx.x;
  const int b = g / DD;
  const int d = g % DD;
  float H = 0.f;
#pragma unroll 4
  for (int c = 0; c < CH; c++) {
    const int idx = (b * CH + c) * DD + d;
    g_Hin[idx] = H;
    H = fmaf(g_Ac[idx], H, g_Xc[idx]);
  }
}

// ---------------- K3c: final rescan + outputs, x fused -----------------------
__global__ __launch_bounds__(256) void k_scan_final(
    const float* __restrict__ v, const float* __restrict__ outp,
    const float* __restrict__ cin, const float* __restrict__ gout,
    const float* __restrict__ gv, float* __restrict__ o_v,
    float* __restrict__ o_out, float* __restrict__ o_c,
    float* __restrict__ o_f) {
  const int d = blockIdx.x * 256 + threadIdx.x;
  const int ch = blockIdx.y;
  const int b = blockIdx.z;
  size_t base = ((size_t)(b * SS + ch * CL)) * DD + d;
  float h = g_Hin[(b * CH + ch) * DD + d];
  const float go = __ldg(&gout[d]);
  const float gvv = __ldg(&gv[d]);
#pragma unroll 4
  for (int t = 0; t < CL; t++) {
    size_t idx = base + (size_t)t * DD;
    float a = g_alpha[idx];
    float vv = v[idx];
    float x = x_of(a, g_beta[idx], vv);
    h = fmaf(a, h, x);
    o_f[idx] = h;
    o_v[idx] = fmaf(h, gvv, vv);
    o_out[idx] = fmaf(h, go, outp[idx]);
    o_c[idx] = cin[idx];
  }
}

// ---------------- launch -----------------------------------------------------
extern "C" void kernel_launch(void* const* d_in, const int* in_sizes, int n_in,
                              void* d_out, int out_size) {
  const float* v = (const float*)d_in[0];
  const float* out = (const float*)d_in[1];
  const float* c = (const float*)d_in[2];
  const float* prev = (const float*)d_in[3];
  const float* Wa = (const float*)d_in[4];
  const float* ba = (const float*)d_in[5];
  const float* Wb = (const float*)d_in[6];
  const float* bb = (const float*)d_in[7];
  const float* gout = (const float*)d_in[8];
  const float* gv = (const float*)d_in[9];

  float* o_v = (float*)d_out;
  float* o_out = o_v + MN;
  float* o_c = o_out + MN;
  float* o_f = o_c + MN;

  // K0 + W conversion (independent)
  k_rmsnorm_split<<<MM, 256>>>(c, prev);
  {
    dim3 wgrid(DD / 32, DD / 32, 2);
    k_cvt_w<<<wgrid, 256>>>(Wa, Wb);
  }

  // K1: dual GEMM via mma.sync (bf16x3)
  {
    dim3 ggrid(32, 64);
    k_gemm_mma<<<ggrid, 256>>>(ba, bb);
  }

  // K3: chunked scan (x fused)
  dim3 agrid(DD / 256, CH, BB);
  k_scan_chunks<<<agrid, 256>>>(v);
  k_scan_carry<<<(BB * DD) / 256, 256>>>();
  k_scan_final<<<agrid, 256>>>(v, out, c, gout, gv, o_v, o_out, o_c, o_f);
}

// round 4
// speedup vs baseline: 2.3149x; 1.0487x over previous
#include <cuda_runtime.h>
#include <cuda_bf16.h>
#include <math.h>
#include <stdint.h>

// Problem constants
#define BB 2
#define SS 4096
#define DD 2048
#define MM (BB * SS)          // 8192 GEMM rows
#define MN ((size_t)MM * DD)  // elements per tensor
#define CH 64                 // scan chunks
#define CL (SS / CH)          // steps per chunk

#define Bb_M 128
#define Bb_N 128
#define Bb_K 32
#define KITERS 192            // 3 * 2048 / 32  (bf16x3 split folded into K)
#define NSTAGE 5
#define STAGE_BYTES 16384

// ---------------- scratch (static device memory) ---------------------------
__device__ __align__(256) __nv_bfloat16 g_gA_hi[MN];
__device__ __align__(256) __nv_bfloat16 g_gA_lo[MN];
__device__ __align__(256) __nv_bfloat16 g_WaT_hi[(size_t)DD * DD];
__device__ __align__(256) __nv_bfloat16 g_WaT_lo[(size_t)DD * DD];
__device__ __align__(256) __nv_bfloat16 g_WbT_hi[(size_t)DD * DD];
__device__ __align__(256) __nv_bfloat16 g_WbT_lo[(size_t)DD * DD];
__device__ __align__(256) float g_alpha[MN];  // sigmoid gate
__device__ __align__(256) float g_beta[MN];   // silu gate
__device__ __align__(256) float g_Ac[BB * CH * DD];
__device__ __align__(256) float g_Xc[BB * CH * DD];
__device__ __align__(256) float g_Hin[BB * CH * DD];

// ---------------- PTX helpers ----------------------------------------------
static __device__ __forceinline__ uint32_t smem_u32(const void* p) {
  uint32_t a;
  asm("{ .reg .u64 t; cvta.to.shared.u64 t, %1; cvt.u32.u64 %0, t; }"
      : "=r"(a) : "l"(p));
  return a;
}

static __device__ __forceinline__ void cpa16(uint32_t dst, const void* src) {
  asm volatile("cp.async.cg.shared.global [%0], [%1], 16;" :: "r"(dst), "l"(src));
}
#define CPA_COMMIT() asm volatile("cp.async.commit_group;" ::: "memory")
#define CPA_WAIT3() asm volatile("cp.async.wait_group 3;" ::: "memory")

static __device__ __forceinline__ void ldmx4(uint32_t* r, uint32_t addr) {
  asm volatile(
      "ldmatrix.sync.aligned.m8n8.x4.shared.b16 {%0, %1, %2, %3}, [%4];"
      : "=r"(r[0]), "=r"(r[1]), "=r"(r[2]), "=r"(r[3]) : "r"(addr));
}

static __device__ __forceinline__ void mma16816(
    float* d, const uint32_t* a, uint32_t b0, uint32_t b1) {
  asm volatile(
      "mma.sync.aligned.m16n8k16.row.col.f32.bf16.bf16.f32 "
      "{%0, %1, %2, %3}, {%4, %5, %6, %7}, {%8, %9}, {%0, %1, %2, %3};"
      : "+f"(d[0]), "+f"(d[1]), "+f"(d[2]), "+f"(d[3])
      : "r"(a[0]), "r"(a[1]), "r"(a[2]), "r"(a[3]), "r"(b0), "r"(b1));
}

// ---------------- K0: gate = rms(c)+rms(prev), split to bf16 hi/lo ----------
static __device__ __forceinline__ void split2(float a, float b,
                                              __nv_bfloat162& h, __nv_bfloat162& l) {
  __nv_bfloat16 ha = __float2bfloat16(a), hb = __float2bfloat16(b);
  h = __halves2bfloat162(ha, hb);
  l = __halves2bfloat162(__float2bfloat16(a - __bfloat162float(ha)),
                         __float2bfloat16(b - __bfloat162float(hb)));
}

__global__ __launch_bounds__(256) void k_rmsnorm_split(
    const float* __restrict__ c, const float* __restrict__ p) {
  const int row = blockIdx.x;
  const int tid = threadIdx.x;
  const float4* c4 = (const float4*)(c + (size_t)row * DD);
  const float4* p4 = (const float4*)(p + (size_t)row * DD);

  float4 cv0 = c4[tid], cv1 = c4[tid + 256];
  float4 pv0 = p4[tid], pv1 = p4[tid + 256];

  float sc = cv0.x * cv0.x + cv0.y * cv0.y + cv0.z * cv0.z + cv0.w * cv0.w +
             cv1.x * cv1.x + cv1.y * cv1.y + cv1.z * cv1.z + cv1.w * cv1.w;
  float sp = pv0.x * pv0.x + pv0.y * pv0.y + pv0.z * pv0.z + pv0.w * pv0.w +
             pv1.x * pv1.x + pv1.y * pv1.y + pv1.z * pv1.z + pv1.w * pv1.w;
#pragma unroll
  for (int off = 16; off > 0; off >>= 1) {
    sc += __shfl_xor_sync(0xffffffffu, sc, off);
    sp += __shfl_xor_sync(0xffffffffu, sp, off);
  }
  __shared__ float ssc[8], ssp[8];
  if ((tid & 31) == 0) { ssc[tid >> 5] = sc; ssp[tid >> 5] = sp; }
  __syncthreads();
  float tc = 0.f, tp = 0.f;
#pragma unroll
  for (int i = 0; i < 8; i++) { tc += ssc[i]; tp += ssp[i]; }
  const float rc = rsqrtf(tc * (1.0f / DD) + 1e-6f);
  const float rp = rsqrtf(tp * (1.0f / DD) + 1e-6f);

  float o[8];
  o[0] = cv0.x * rc + pv0.x * rp; o[1] = cv0.y * rc + pv0.y * rp;
  o[2] = cv0.z * rc + pv0.z * rp; o[3] = cv0.w * rc + pv0.w * rp;
  o[4] = cv1.x * rc + pv1.x * rp; o[5] = cv1.y * rc + pv1.y * rp;
  o[6] = cv1.z * rc + pv1.z * rp; o[7] = cv1.w * rc + pv1.w * rp;

  __nv_bfloat162* h2 = (__nv_bfloat162*)(g_gA_hi + (size_t)row * DD);
  __nv_bfloat162* l2 = (__nv_bfloat162*)(g_gA_lo + (size_t)row * DD);
  __nv_bfloat162 h, l;
  split2(o[0], o[1], h, l); h2[2 * tid + 0] = h; l2[2 * tid + 0] = l;
  split2(o[2], o[3], h, l); h2[2 * tid + 1] = h; l2[2 * tid + 1] = l;
  split2(o[4], o[5], h, l); h2[2 * (tid + 256) + 0] = h; l2[2 * (tid + 256) + 0] = l;
  split2(o[6], o[7], h, l); h2[2 * (tid + 256) + 1] = h; l2[2 * (tid + 256) + 1] = l;
}

// ---------------- K_w: transpose + bf16 split of W --------------------------
__global__ __launch_bounds__(256) void k_cvt_w(
    const float* __restrict__ Wa, const float* __restrict__ Wb) {
  __shared__ float t[32][33];
  const int mat = blockIdx.z;
  const float* __restrict__ W = mat ? Wb : Wa;
  __nv_bfloat16* __restrict__ Th = mat ? g_WbT_hi : g_WaT_hi;
  __nv_bfloat16* __restrict__ Tl = mat ? g_WbT_lo : g_WaT_lo;
  const int bx = blockIdx.x * 32;  // n base
  const int by = blockIdx.y * 32;  // k base
  const int x = threadIdx.x & 31, y0 = threadIdx.x >> 5;
#pragma unroll
  for (int i = 0; i < 4; i++) {
    int y = y0 + i * 8;
    t[y][x] = W[(size_t)(by + y) * DD + bx + x];  // W[k][n]
  }
  __syncthreads();
#pragma unroll
  for (int i = 0; i < 4; i++) {
    int y = y0 + i * 8;
    float v = t[x][y];  // WT[n=bx+y][k=by+x]
    __nv_bfloat16 h = __float2bfloat16(v);
    size_t idx = (size_t)(bx + y) * DD + by + x;
    Th[idx] = h;
    Tl[idx] = __float2bfloat16(v - __bfloat162float(h));
  }
}

// ---------------- K1: mma.sync dual GEMM, bf16x3, 5-stage pipeline ----------
// grid.x: 0..15 -> W_alpha/sigmoid N-tiles, 16..31 -> W_beta/silu N-tiles
// grid.y: 64 M-tiles. 128x128x32 CTA tile, 8 warps each 64x32.
__global__ __launch_bounds__(256, 2) void k_gemm_mma(
    const float* __restrict__ ba, const float* __restrict__ bb) {
  extern __shared__ __align__(1024) char sm[];  // NSTAGE * (8KB A + 8KB B)
  const uint32_t smb = smem_u32(sm);

  const int tid = threadIdx.x;
  const int wid = tid >> 5, lid = tid & 31;
  const int bxv = blockIdx.x;
  const bool isBeta = (bxv >= 16);
  const int n0 = (isBeta ? bxv - 16 : bxv) * Bb_N;
  const int m0 = blockIdx.y * Bb_M;
  const __nv_bfloat16* __restrict__ Bhi = isBeta ? g_WbT_hi : g_WaT_hi;
  const __nv_bfloat16* __restrict__ Blo = isBeta ? g_WbT_lo : g_WaT_lo;
  const float* __restrict__ bias = isBeta ? bb : ba;

  // cp.async slots: 2 A chunks + 2 B chunks of 16B per thread per stage
  uint32_t a_sm[2], b_sm[2];
  size_t a_gl[2], b_gl[2];
#pragma unroll
  for (int i = 0; i < 2; i++) {
    int id = tid + i * 256;      // 0..511
    int row = id >> 2, cc = id & 3;
    uint32_t sw = (uint32_t)((cc ^ ((row >> 1) & 3)) << 4);
    a_sm[i] = row * 64 + sw;
    b_sm[i] = row * 64 + sw;
    a_gl[i] = (size_t)(m0 + row) * DD + cc * 8;
    b_gl[i] = (size_t)(n0 + row) * DD + cc * 8;
  }

  auto load_stage = [&](int kc, int buf) {
    const int seg = kc >> 6;            // 64 k-chunks per segment
    const int kk = (kc & 63) * Bb_K;
    const __nv_bfloat16* __restrict__ As = (seg == 1) ? g_gA_lo : g_gA_hi;
    const __nv_bfloat16* __restrict__ Bs = (seg == 2) ? Blo : Bhi;
    const uint32_t ab = smb + buf * STAGE_BYTES;
    const uint32_t bbuf = ab + 8192;
#pragma unroll
    for (int i = 0; i < 2; i++) cpa16(ab + a_sm[i], As + a_gl[i] + kk);
#pragma unroll
    for (int i = 0; i < 2; i++) cpa16(bbuf + b_sm[i], Bs + b_gl[i] + kk);
  };

  // warp tiling: wm in {0,1} (64 rows), wn in {0..3} (32 cols)
  const int wm = wid & 1, wn = wid >> 1;
  const int lr = lid & 15, c8 = lid >> 4;

  uint32_t a_off[4], a_swz[4];
#pragma unroll
  for (int mt = 0; mt < 4; mt++) {
    int row = wm * 64 + mt * 16 + lr;
    a_off[mt] = row * 64;
    a_swz[mt] = (row >> 1) & 3;
  }
  uint32_t b_off[2], b_swz[2];
#pragma unroll
  for (int bt = 0; bt < 2; bt++) {
    int row = wn * 32 + bt * 16 + lr;
    b_off[bt] = row * 64;
    b_swz[bt] = (row >> 1) & 3;
  }

  float ac[4][4][4];
#pragma unroll
  for (int i = 0; i < 4; i++)
#pragma unroll
    for (int j = 0; j < 4; j++)
#pragma unroll
      for (int q = 0; q < 4; q++) ac[i][j][q] = 0.f;

  // prefetch first NSTAGE-1 stages
#pragma unroll
  for (int s = 0; s < NSTAGE - 1; s++) { load_stage(s, s); CPA_COMMIT(); }

  int cmp_buf = 0, ld_buf = NSTAGE - 1;
#pragma unroll 1
  for (int kc = 0; kc < KITERS; kc++) {
    CPA_WAIT3();
    __syncthreads();

    // issue prefetch for kc+NSTAGE-1 first (overlaps with compute below)
    if (kc + NSTAGE - 1 < KITERS) load_stage(kc + NSTAGE - 1, ld_buf);
    CPA_COMMIT();

    const uint32_t abase = smb + cmp_buf * STAGE_BYTES;
    const uint32_t bbase = abase + 8192;

#pragma unroll
    for (int ks = 0; ks < 2; ks++) {
      const uint32_t chunk = (uint32_t)(ks * 2 + c8);
      uint32_t af[4][4], bfr[2][4];
#pragma unroll
      for (int mt = 0; mt < 4; mt++)
        ldmx4(af[mt], abase + a_off[mt] + ((chunk ^ a_swz[mt]) << 4));
#pragma unroll
      for (int bt = 0; bt < 2; bt++)
        ldmx4(bfr[bt], bbase + b_off[bt] + ((chunk ^ b_swz[bt]) << 4));
#pragma unroll
      for (int mt = 0; mt < 4; mt++) {
#pragma unroll
        for (int nt = 0; nt < 4; nt++) {
          const int bt = nt >> 1, sel = nt & 1;
          mma16816(ac[mt][nt], af[mt], bfr[bt][sel], bfr[bt][2 + sel]);
        }
      }
    }

    cmp_buf = (cmp_buf + 1 == NSTAGE) ? 0 : cmp_buf + 1;
    ld_buf = (ld_buf + 1 == NSTAGE) ? 0 : ld_buf + 1;
  }

  // epilogue: bias + sigmoid/silu, direct global store
  float* __restrict__ dst = isBeta ? g_beta : g_alpha;
  const int g = lid >> 2, tig = lid & 3;
  float bi0[4], bi1[4];
#pragma unroll
  for (int nt = 0; nt < 4; nt++) {
    int col = n0 + wn * 32 + nt * 8 + tig * 2;
    bi0[nt] = __ldg(bias + col);
    bi1[nt] = __ldg(bias + col + 1);
  }
#pragma unroll
  for (int mt = 0; mt < 4; mt++) {
    const int row = m0 + wm * 64 + mt * 16 + g;
#pragma unroll
    for (int nt = 0; nt < 4; nt++) {
      const int col = n0 + wn * 32 + nt * 8 + tig * 2;
      float pr, sg;
      float2 v0, v1;
      pr = ac[mt][nt][0] + bi0[nt];
      sg = 1.0f / (1.0f + __expf(-pr)); v0.x = isBeta ? pr * sg : sg;
      pr = ac[mt][nt][1] + bi1[nt];
      sg = 1.0f / (1.0f + __expf(-pr)); v0.y = isBeta ? pr * sg : sg;
      pr = ac[mt][nt][2] + bi0[nt];
      sg = 1.0f / (1.0f + __expf(-pr)); v1.x = isBeta ? pr * sg : sg;
      pr = ac[mt][nt][3] + bi1[nt];
      sg = 1.0f / (1.0f + __expf(-pr)); v1.y = isBeta ? pr * sg : sg;
      *(float2*)(dst + (size_t)row * DD + col) = v0;
      *(float2*)(dst + (size_t)(row + 8) * DD + col) = v1;
    }
  }
}

// ---------------- x helper ---------------------------------------------------
static __device__ __forceinline__ float x_of(float a, float be, float vv) {
  return vv * be * sqrtf(fmaxf(1.0f - a * a, 1e-6f));
}

// ---------------- K3a: per-chunk (A_prod, X_scan), x fused -------------------
__global__ __launch_bounds__(256) void k_scan_chunks(const float* __restrict__ v) {
  const int d = blockIdx.x * 256 + threadIdx.x;
  const int ch = blockIdx.y;
  const int b = blockIdx.z;
  size_t base = ((size_t)(b * SS + ch * CL)) * DD + d;
  float A = 1.f, X = 0.f;
#pragma unroll 4
  for (int t = 0; t < CL; t++) {
    size_t idx = base + (size_t)t * DD;
    float a = g_alpha[idx];
    float x = x_of(a, g_beta[idx], v[idx]);
    X = fmaf(a, X, x);
    A *= a;
  }
  const int o = (b * CH + ch) * DD + d;
  g_Ac[o] = A;
  g_Xc[o] = X;
}

// ---------------- K3b: carry scan across chunks ------------------------------
__global__ __launch_bounds__(256) void k_scan_carry() {
  const int g = blockIdx.x * 256 + threadIdx.x;
  const int b = g / DD;
  const int d = g % DD;
  float H = 0.f;
#pragma unroll 4
  for (int c = 0; c < CH; c++) {
    const int idx = (b * CH + c) * DD + d;
    g_Hin[idx] = H;
    H = fmaf(g_Ac[idx], H, g_Xc[idx]);
  }
}

// ---------------- K3c: final rescan + outputs, x fused -----------------------
__global__ __launch_bounds__(256) void k_scan_final(
    const float* __restrict__ v, const float* __restrict__ outp,
    const float* __restrict__ cin, const float* __restrict__ gout,
    const float* __restrict__ gv, float* __restrict__ o_v,
    float* __restrict__ o_out, float* __restrict__ o_c,
    float* __restrict__ o_f) {
  const int d = blockIdx.x * 256 + threadIdx.x;
  const int ch = blockIdx.y;
  const int b = blockIdx.z;
  size_t base = ((size_t)(b * SS + ch * CL)) * DD + d;
  float h = g_Hin[(b * CH + ch) * DD + d];
  const float go = __ldg(&gout[d]);
  const float gvv = __ldg(&gv[d]);
#pragma unroll 4
  for (int t = 0; t < CL; t++) {
    size_t idx = base + (size_t)t * DD;
    float a = g_alpha[idx];
    float vv = v[idx];
    float x = x_of(a, g_beta[idx], vv);
    h = fmaf(a, h, x);
    o_f[idx] = h;
    o_v[idx] = fmaf(h, gvv, vv);
    o_out[idx] = fmaf(h, go, outp[idx]);
    o_c[idx] = cin[idx];
  }
}

// ---------------- launch -----------------------------------------------------
extern "C" void kernel_launch(void* const* d_in, const int* in_sizes, int n_in,
                              void* d_out, int out_size) {
  const float* v = (const float*)d_in[0];
  const float* out = (const float*)d_in[1];
  const float* c = (const float*)d_in[2];
  const float* prev = (const float*)d_in[3];
  const float* Wa = (const float*)d_in[4];
  const float* ba = (const float*)d_in[5];
  const float* Wb = (const float*)d_in[6];
  const float* bb = (const float*)d_in[7];
  const float* gout = (const float*)d_in[8];
  const float* gv = (const float*)d_in[9];

  float* o_v = (float*)d_out;
  float* o_out = o_v + MN;
  float* o_c = o_out + MN;
  float* o_f = o_c + MN;

  // K0 + W conversion (independent)
  k_rmsnorm_split<<<MM, 256>>>(c, prev);
  {
    dim3 wgrid(DD / 32, DD / 32, 2);
    k_cvt_w<<<wgrid, 256>>>(Wa, Wb);
  }

  // K1: dual GEMM via mma.sync (bf16x3), 5-stage cp.async pipeline
  {
    const int SMEM_BYTES = NSTAGE * STAGE_BYTES;  // 80 KB
    cudaFuncSetAttribute(k_gemm_mma, cudaFuncAttributeMaxDynamicSharedMemorySize,
                         SMEM_BYTES);
    dim3 ggrid(32, 64);
    k_gemm_mma<<<ggrid, 256, SMEM_BYTES>>>(ba, bb);
  }

  // K3: chunked scan (x fused)
  dim3 agrid(DD / 256, CH, BB);
  k_scan_chunks<<<agrid, 256>>>(v);
  k_scan_carry<<<(BB * DD) / 256, 256>>>();
  k_scan_final<<<agrid, 256>>>(v, out, c, gout, gv, o_v, o_out, o_c, o_f);
}